// round 5
// baseline (speedup 1.0000x reference)
#include <cuda_runtime.h>
#include <cuda_fp16.h>
#include <cstdint>

#define B_TOT 8192
#define NSM   148

// ---------------- device scratch ----------------
__device__ __align__(16) __half g_W2f[256 * 256];
__device__ __align__(16) __half g_W1f[256 * 256];
__device__ __align__(16) __half g_W3T[256 * 64];
__device__ __align__(16) __half g_U[(size_t)B_TOT * 256 * 64];   // compacted U per sample
__device__ __align__(16) float  g_f[B_TOT * 64];
__device__ unsigned g_r1[B_TOT * 8];
__device__ unsigned g_r2[B_TOT * 8];

// ---------------- helpers ----------------
__device__ __forceinline__ uint32_t smem_u32(const void* p) {
    uint32_t a;
    asm("{ .reg .u64 t; cvta.to.shared.u64 t, %1; cvt.u32.u64 %0, t; }" : "=r"(a) : "l"(p));
    return a;
}
__device__ __forceinline__ void cp16(uint32_t dst, const void* src) {
    asm volatile("cp.async.cg.shared.global [%0], [%1], 16;" :: "r"(dst), "l"(src) : "memory");
}
#define CP_COMMIT() asm volatile("cp.async.commit_group;" ::: "memory")
#define CP_WAIT0()  asm volatile("cp.async.wait_group 0;" ::: "memory")
__device__ __forceinline__ void ldm4t(uint32_t& r0, uint32_t& r1, uint32_t& r2, uint32_t& r3,
                                      uint32_t addr) {
    asm volatile("ldmatrix.sync.aligned.m8n8.x4.trans.shared.b16 {%0,%1,%2,%3}, [%4];"
                 : "=r"(r0), "=r"(r1), "=r"(r2), "=r"(r3) : "r"(addr));
}
__device__ __forceinline__ void mma16816(float c[4], uint32_t a0, uint32_t a1,
                                         uint32_t a2, uint32_t a3,
                                         uint32_t b0, uint32_t b1) {
    asm volatile(
        "mma.sync.aligned.m16n8k16.row.col.f32.f16.f16.f32 "
        "{%0,%1,%2,%3}, {%4,%5,%6,%7}, {%8,%9}, {%0,%1,%2,%3};"
        : "+f"(c[0]), "+f"(c[1]), "+f"(c[2]), "+f"(c[3])
        : "r"(a0), "r"(a1), "r"(a2), "r"(a3), "r"(b0), "r"(b1));
}

// =====================================================================
// prep: f16 copies (k-row-major everywhere)
// =====================================================================
__global__ void prep_kernel(const float* __restrict__ W1, const float* __restrict__ W2,
                            const float* __restrict__ W3) {
    int idx = blockIdx.x * 256 + threadIdx.x;
    if (idx < 65536) g_W2f[idx] = __float2half_rn(W2[idx]);
    else if (idx < 131072) g_W1f[idx - 65536] = __float2half_rn(W1[idx - 65536]);
    else {
        int l = idx - 131072;
        int i = l >> 6, o = l & 63;
        g_W3T[l] = __float2half_rn(W3[o * 256 + i]);
    }
}

// =====================================================================
// forward MLP (fp32 exact) + ReLU bitmasks, 16 samples / block
// =====================================================================
__global__ __launch_bounds__(256) void fwd_kernel(
    const float* __restrict__ X,
    const float* __restrict__ W1, const float* __restrict__ B1,
    const float* __restrict__ W2, const float* __restrict__ B2,
    const float* __restrict__ W3, const float* __restrict__ B3)
{
    __shared__ float bufA[16][256];
    __shared__ float bufB[16][256];
    const int t = threadIdx.x, lane = t & 31, wid = t >> 5;
    const int s0 = blockIdx.x * 16;

    {
        const float4* src = (const float4*)(X + (size_t)s0 * 256);
        float4* dst = (float4*)&bufA[0][0];
        for (int i = t; i < 16 * 64; i += 256) dst[i] = __ldg(src + i);
    }
    __syncthreads();

    float acc[16];
    {   // layer 1
        #pragma unroll
        for (int s = 0; s < 16; ++s) acc[s] = 0.f;
        const float4* wr = (const float4*)(W1 + t * 256);
        for (int j = 0; j < 64; ++j) {
            float4 w = __ldg(wr + j);
            #pragma unroll
            for (int s = 0; s < 16; ++s) {
                float4 xv = ((const float4*)bufA[s])[j];
                acc[s] = fmaf(w.x, xv.x, acc[s]); acc[s] = fmaf(w.y, xv.y, acc[s]);
                acc[s] = fmaf(w.z, xv.z, acc[s]); acc[s] = fmaf(w.w, xv.w, acc[s]);
            }
        }
        const float b = __ldg(B1 + t);
        #pragma unroll
        for (int s = 0; s < 16; ++s) {
            float z = acc[s] + b;
            unsigned m = __ballot_sync(0xffffffffu, z > 0.f);
            if (lane == 0) g_r1[(size_t)(s0 + s) * 8 + wid] = m;
            bufB[s][t] = z > 0.f ? z : 0.f;
        }
    }
    __syncthreads();
    {   // layer 2
        #pragma unroll
        for (int s = 0; s < 16; ++s) acc[s] = 0.f;
        const float4* wr = (const float4*)(W2 + t * 256);
        for (int j = 0; j < 64; ++j) {
            float4 w = __ldg(wr + j);
            #pragma unroll
            for (int s = 0; s < 16; ++s) {
                float4 xv = ((const float4*)bufB[s])[j];
                acc[s] = fmaf(w.x, xv.x, acc[s]); acc[s] = fmaf(w.y, xv.y, acc[s]);
                acc[s] = fmaf(w.z, xv.z, acc[s]); acc[s] = fmaf(w.w, xv.w, acc[s]);
            }
        }
        const float b = __ldg(B2 + t);
        #pragma unroll
        for (int s = 0; s < 16; ++s) {
            float z = acc[s] + b;
            unsigned m = __ballot_sync(0xffffffffu, z > 0.f);
            if (lane == 0) g_r2[(size_t)(s0 + s) * 8 + wid] = m;
            bufA[s][t] = z > 0.f ? z : 0.f;
        }
    }
    __syncthreads();
    {   // layer 3
        const int o = t & 63, sg = t >> 6;
        float a4[4] = {0.f, 0.f, 0.f, 0.f};
        const float4* wr = (const float4*)(W3 + o * 256);
        for (int j = 0; j < 64; ++j) {
            float4 w = __ldg(wr + j);
            #pragma unroll
            for (int q = 0; q < 4; ++q) {
                float4 hv = ((const float4*)bufA[sg * 4 + q])[j];
                a4[q] = fmaf(w.x, hv.x, a4[q]); a4[q] = fmaf(w.y, hv.y, a4[q]);
                a4[q] = fmaf(w.z, hv.z, a4[q]); a4[q] = fmaf(w.w, hv.w, a4[q]);
            }
        }
        const float b = __ldg(B3 + o);
        #pragma unroll
        for (int q = 0; q < 4; ++q)
            g_f[(size_t)(s0 + sg * 4 + q) * 64 + o] = a4[q] + b;
    }
}

// =====================================================================
// Kernel A: persistent GEMM1  U = (W3 D2) W2 -> compacted to g_U
// Resident: W3T (257 x 144B), W2 (257 x 528B), Ustage (256 x 128B)
// =====================================================================
#define A_W3T 0u
#define A_W2  37008u
#define A_UST 172704u
#define A_MSC 205472u
#define SMEMA 206768

__global__ __launch_bounds__(256, 1) void gemm1_kernel() {
    extern __shared__ char smem[];
    const uint32_t sb = smem_u32(smem);
    const int tid = threadIdx.x, lane = tid & 31, wid = tid >> 5;
    const int g = lane >> 2, tig = lane & 3;
    const int wm = wid & 1, wn = wid >> 1;

    unsigned* mbuf = (unsigned*)(smem + A_MSC);          // 2 x 16 words
    unsigned* m2s  = mbuf + 32;
    unsigned* m1s  = m2s + 8;
    unsigned* p2s  = m1s + 8;                            // 9 (+1 pad)
    unsigned* p1s  = p2s + 10;                           // 9 (+1 pad)
    unsigned short* idx2 = (unsigned short*)(p1s + 10);  // 256
    unsigned short* pos1 = idx2 + 256;                   // 256

    // ---- resident load ----
    for (int c = tid; c < 2048; c += 256)
        cp16(sb + A_W3T + (uint32_t)(c >> 3) * 144u + (uint32_t)(c & 7) * 16u,
             (const char*)g_W3T + (size_t)c * 16);
    for (int c = tid; c < 8192; c += 256)
        cp16(sb + A_W2 + (uint32_t)(c >> 5) * 528u + (uint32_t)(c & 31) * 16u,
             (const char*)g_W2f + (size_t)c * 16);
    CP_COMMIT();
    if (tid < 9)       *(uint4*)(smem + A_W3T + 256 * 144 + tid * 16) = make_uint4(0,0,0,0);
    else if (tid < 42) *(uint4*)(smem + A_W2 + 256 * 528 + (tid - 9) * 16) = make_uint4(0,0,0,0);

    // first masks prefetch
    const int s0 = blockIdx.x;
    if (tid < 2)      cp16(sb + A_MSC + tid * 16u, (const char*)(g_r2 + (size_t)s0 * 8) + tid * 16);
    else if (tid < 4) cp16(sb + A_MSC + tid * 16u, (const char*)(g_r1 + (size_t)s0 * 8) + (tid - 2) * 16);
    CP_COMMIT();

    const uint32_t aCol = ((lane >> 3) & 1) * 16 + wm * 64;
    const uint32_t bCol = ((lane >> 4) & 1) * 16 + wn * 128;
    const int rlA = (lane & 7) + ((lane >> 4) & 1) * 8;
    const int rlB = (lane & 7) + ((lane >> 3) & 1) * 8;

    int it = 0;
    for (int s = s0; s < B_TOT; s += NSM, ++it) {
        const int pb = it & 1;
        CP_WAIT0();
        __syncthreads();
        if (tid < 8)       m2s[tid] = mbuf[pb * 16 + tid];
        else if (tid < 16) m1s[tid - 8] = mbuf[pb * 16 + tid];
        __syncthreads();
        // prefetch next masks
        {
            const int sn = s + NSM;
            if (sn < B_TOT) {
                const uint32_t mb = sb + A_MSC + (uint32_t)(pb ^ 1) * 64u;
                if (tid < 2)      cp16(mb + tid * 16u, (const char*)(g_r2 + (size_t)sn * 8) + tid * 16);
                else if (tid < 4) cp16(mb + tid * 16u, (const char*)(g_r1 + (size_t)sn * 8) + (tid - 2) * 16);
            }
            CP_COMMIT();
        }
        if (tid == 0)  { unsigned p = 0; for (int w = 0; w < 8; ++w) { p2s[w] = p; p += __popc(m2s[w]); } p2s[8] = p; }
        if (tid == 32) { unsigned p = 0; for (int w = 0; w < 8; ++w) { p1s[w] = p; p += __popc(m1s[w]); } p1s[8] = p; }
        __syncthreads();
        const int n2 = p2s[8], n1 = p1s[8];
        const int nk2 = (n2 + 15) >> 4, nk1 = (n1 + 15) >> 4;
        {
            const int w = tid >> 5, bi = tid & 31;
            const unsigned below = (bi == 0) ? 0u : ((1u << bi) - 1u);
            if ((m2s[w] >> bi) & 1u)
                idx2[p2s[w] + __popc(m2s[w] & below)] = (unsigned short)tid;
            if ((m1s[w] >> bi) & 1u)
                pos1[tid] = (unsigned short)(p1s[w] + __popc(m1s[w] & below));
            if (tid >= n2 && tid < nk2 * 16) idx2[tid] = 256;  // zero row
        }
        // zero Ustage pad rows [n1, nk1*16)
        for (int i = tid; i < (nk1 * 16 - n1) * 8; i += 256) {
            const int r = n1 + (i >> 3), sg = i & 7;
            *(uint4*)(smem + A_UST + (uint32_t)r * 128u + (uint32_t)sg * 16u) = make_uint4(0,0,0,0);
        }
        __syncthreads();

        // ---- GEMM1: C[64][256] over K = n2 (gathered) ----
        float acc[2][8][4];
        #pragma unroll
        for (int mt = 0; mt < 2; ++mt)
            #pragma unroll
            for (int nt = 0; nt < 8; ++nt)
                #pragma unroll
                for (int q = 0; q < 4; ++q) acc[mt][nt][q] = 0.f;

        for (int kt = 0; kt < nk2; ++kt) {
            const uint32_t rA = idx2[kt * 16 + rlA];
            const uint32_t rB = idx2[kt * 16 + rlB];
            const uint32_t aadr = sb + A_W3T + rA * 144u + aCol;
            const uint32_t badr = sb + A_W2 + rB * 528u + bCol;
            uint32_t a[2][4], b[4][4];
            #pragma unroll
            for (int mt = 0; mt < 2; ++mt)
                ldm4t(a[mt][0], a[mt][1], a[mt][2], a[mt][3], aadr + (uint32_t)mt * 32u);
            #pragma unroll
            for (int ng = 0; ng < 4; ++ng)
                ldm4t(b[ng][0], b[ng][1], b[ng][2], b[ng][3], badr + (uint32_t)ng * 32u);
            #pragma unroll
            for (int mt = 0; mt < 2; ++mt)
                #pragma unroll
                for (int nt = 0; nt < 8; ++nt)
                    mma16816(acc[mt][nt], a[mt][0], a[mt][1], a[mt][2], a[mt][3],
                             b[nt >> 1][(nt & 1) * 2], b[nt >> 1][(nt & 1) * 2 + 1]);
        }

        // ---- scatter masked U into Ustage (compacted rows) ----
        #pragma unroll
        for (int mt = 0; mt < 2; ++mt)
            #pragma unroll
            for (int nt = 0; nt < 8; ++nt)
                #pragma unroll
                for (int q = 0; q < 4; ++q) {
                    const int m = wm * 32 + mt * 16 + g + (q >> 1) * 8;
                    const int j = wn * 64 + nt * 8 + 2 * tig + (q & 1);
                    if ((m1s[j >> 5] >> (j & 31)) & 1u)
                        *(__half*)(smem + A_UST + (uint32_t)pos1[j] * 128u + (uint32_t)m * 2u) =
                            __float2half_rn(acc[mt][nt][q]);
                }
        __syncthreads();

        // ---- copy out nk1*16 rows ----
        {
            char* dst = (char*)(g_U + (size_t)s * 16384);
            for (int i = tid; i < nk1 * 16 * 8; i += 256)
                *(uint4*)(dst + (size_t)i * 16) = *(uint4*)(smem + A_UST + (uint32_t)i * 16u);
        }
    }
}

// =====================================================================
// Kernel B: persistent GEMM2  V = U W1, ||V||^2, epilogue
// Resident: W1 (257 x 528B); Ubuf 2 x (256 x 144B)
// =====================================================================
#define B_W1  0u
#define B_UB  135696u
#define B_MSC 209424u
#define SMEMB 210704

__global__ __launch_bounds__(256, 1) void gemm2_kernel(const float* __restrict__ Kp,
                                                       float* __restrict__ out) {
    extern __shared__ char smem[];
    const uint32_t sb = smem_u32(smem);
    const int tid = threadIdx.x, lane = tid & 31, wid = tid >> 5;
    const int wm = wid & 1, wn = wid >> 1;

    unsigned* mbuf = (unsigned*)(smem + B_MSC);            // 2 x 8 words
    float*    fbuf = (float*)(mbuf + 16);                  // 2 x 64
    unsigned* m1s  = (unsigned*)(fbuf + 128);              // 8
    unsigned* p1s  = m1s + 8;                              // 9 (+1 pad)
    unsigned short* idx1 = (unsigned short*)(p1s + 10);    // 256
    float*    red  = (float*)(idx1 + 256);                 // 8

    // resident W1
    for (int c = tid; c < 8192; c += 256)
        cp16(sb + B_W1 + (uint32_t)(c >> 5) * 528u + (uint32_t)(c & 31) * 16u,
             (const char*)g_W1f + (size_t)c * 16);
    CP_COMMIT();
    if (tid < 33) *(uint4*)(smem + B_W1 + 256 * 528 + tid * 16) = make_uint4(0,0,0,0);

    // first prefetch: masks + f + U(256 rows)
    const int s0 = blockIdx.x;
    {
        if (tid < 2)       cp16(sb + B_MSC + tid * 16u, (const char*)(g_r1 + (size_t)s0 * 8) + tid * 16);
        else if (tid < 18) cp16(sb + B_MSC + 64u + (tid - 2) * 16u,
                                (const char*)(g_f + (size_t)s0 * 64) + (tid - 2) * 16);
        for (int c = tid; c < 2048; c += 256)
            cp16(sb + B_UB + (uint32_t)(c >> 3) * 144u + (uint32_t)(c & 7) * 16u,
                 (const char*)(g_U + (size_t)s0 * 16384) + (size_t)c * 16);
        CP_COMMIT();
    }

    const float kk = __ldg(Kp);
    const float sp = (kk > 20.f) ? kk : log1pf(expf(kk));

    const uint32_t aCol = ((lane >> 3) & 1) * 16 + wm * 64;
    const uint32_t bCol = ((lane >> 4) & 1) * 16 + wn * 128;
    const int rlA = (lane & 7) + ((lane >> 4) & 1) * 8;
    const int rlB = (lane & 7) + ((lane >> 3) & 1) * 8;

    int it = 0;
    for (int s = s0; s < B_TOT; s += NSM, ++it) {
        const int pb = it & 1;
        CP_WAIT0();
        __syncthreads();
        if (tid < 8) m1s[tid] = mbuf[pb * 8 + tid];
        __syncthreads();
        // prefetch next sample
        {
            const int sn = s + NSM;
            if (sn < B_TOT) {
                const uint32_t mb = sb + B_MSC + (uint32_t)(pb ^ 1) * 32u;
                const uint32_t fb = sb + B_MSC + 64u + (uint32_t)(pb ^ 1) * 256u;
                const uint32_t ub = sb + B_UB + (uint32_t)(pb ^ 1) * 36864u;
                if (tid < 2)       cp16(mb + tid * 16u, (const char*)(g_r1 + (size_t)sn * 8) + tid * 16);
                else if (tid < 18) cp16(fb + (tid - 2) * 16u,
                                        (const char*)(g_f + (size_t)sn * 64) + (tid - 2) * 16);
                for (int c = tid; c < 2048; c += 256)
                    cp16(ub + (uint32_t)(c >> 3) * 144u + (uint32_t)(c & 7) * 16u,
                         (const char*)(g_U + (size_t)sn * 16384) + (size_t)c * 16);
            }
            CP_COMMIT();
        }
        if (tid == 0) { unsigned p = 0; for (int w = 0; w < 8; ++w) { p1s[w] = p; p += __popc(m1s[w]); } p1s[8] = p; }
        __syncthreads();
        const int n1 = p1s[8];
        const int nk1 = (n1 + 15) >> 4;
        {
            const int w = tid >> 5, bi = tid & 31;
            const unsigned below = (bi == 0) ? 0u : ((1u << bi) - 1u);
            if ((m1s[w] >> bi) & 1u)
                idx1[p1s[w] + __popc(m1s[w] & below)] = (unsigned short)tid;
            if (tid >= n1 && tid < nk1 * 16) idx1[tid] = 256;
        }
        __syncthreads();

        // ---- GEMM2: V[64][256] over K = n1 ----
        float acc[2][8][4];
        #pragma unroll
        for (int mt = 0; mt < 2; ++mt)
            #pragma unroll
            for (int nt = 0; nt < 8; ++nt)
                #pragma unroll
                for (int q = 0; q < 4; ++q) acc[mt][nt][q] = 0.f;

        const uint32_t ubase = sb + B_UB + (uint32_t)pb * 36864u;
        for (int kt = 0; kt < nk1; ++kt) {
            const uint32_t rB = idx1[kt * 16 + rlB];
            const uint32_t aadr = ubase + (uint32_t)(kt * 16 + rlA) * 144u + aCol;
            const uint32_t badr = sb + B_W1 + rB * 528u + bCol;
            uint32_t a[2][4], b[4][4];
            #pragma unroll
            for (int mt = 0; mt < 2; ++mt)
                ldm4t(a[mt][0], a[mt][1], a[mt][2], a[mt][3], aadr + (uint32_t)mt * 32u);
            #pragma unroll
            for (int ng = 0; ng < 4; ++ng)
                ldm4t(b[ng][0], b[ng][1], b[ng][2], b[ng][3], badr + (uint32_t)ng * 32u);
            #pragma unroll
            for (int mt = 0; mt < 2; ++mt)
                #pragma unroll
                for (int nt = 0; nt < 8; ++nt)
                    mma16816(acc[mt][nt], a[mt][0], a[mt][1], a[mt][2], a[mt][3],
                             b[nt >> 1][(nt & 1) * 2], b[nt >> 1][(nt & 1) * 2 + 1]);
        }

        float ss = 0.f;
        #pragma unroll
        for (int mt = 0; mt < 2; ++mt)
            #pragma unroll
            for (int nt = 0; nt < 8; ++nt)
                #pragma unroll
                for (int q = 0; q < 4; ++q)
                    ss = fmaf(acc[mt][nt][q], acc[mt][nt][q], ss);
        #pragma unroll
        for (int off = 16; off; off >>= 1)
            ss += __shfl_xor_sync(0xffffffffu, ss, off);
        if (lane == 0) red[wid] = ss;
        __syncthreads();

        if (tid < 64) {
            const float jn2 = red[0] + red[1] + red[2] + red[3] +
                              red[4] + red[5] + red[6] + red[7];
            const float fv = fbuf[pb * 64 + tid];
            out[(size_t)s * 64 + tid] = tanhf(sp * fv / (sqrtf(jn2) + 1e-4f));
        }
    }
}

// =====================================================================
extern "C" void kernel_launch(void* const* d_in, const int* in_sizes, int n_in,
                              void* d_out, int out_size)
{
    const float* X  = (const float*)d_in[0];
    const float* W1 = (const float*)d_in[1];
    const float* B1 = (const float*)d_in[2];
    const float* W2 = (const float*)d_in[3];
    const float* B2 = (const float*)d_in[4];
    const float* W3 = (const float*)d_in[5];
    const float* B3 = (const float*)d_in[6];
    const float* Kp = (const float*)d_in[7];
    float* out = (float*)d_out;

    cudaFuncSetAttribute(gemm1_kernel, cudaFuncAttributeMaxDynamicSharedMemorySize, SMEMA);
    cudaFuncSetAttribute(gemm2_kernel, cudaFuncAttributeMaxDynamicSharedMemorySize, SMEMB);

    prep_kernel<<<576, 256>>>(W1, W2, W3);
    fwd_kernel<<<B_TOT / 16, 256>>>(X, W1, B1, W2, B2, W3, B3);
    gemm1_kernel<<<NSM, 256, SMEMA>>>();
    gemm2_kernel<<<NSM, 256, SMEMB>>>(Kp, out);
}

// round 6
// speedup vs baseline: 1.0729x; 1.0729x over previous
#include <cuda_runtime.h>
#include <cuda_fp16.h>
#include <cstdint>

#define B_TOT 8192
#define NSM   148

// ---------------- device scratch ----------------
__device__ __align__(16) __half g_W2f[256 * 256];
__device__ __align__(16) __half g_W1f[256 * 256];
__device__ __align__(16) __half g_W3T[256 * 64];
__device__ __align__(16) float  g_f[B_TOT * 64];
__device__ unsigned g_r1[B_TOT * 8];
__device__ unsigned g_r2[B_TOT * 8];

// ---------------- helpers ----------------
__device__ __forceinline__ uint32_t smem_u32(const void* p) {
    uint32_t a;
    asm("{ .reg .u64 t; cvta.to.shared.u64 t, %1; cvt.u32.u64 %0, t; }" : "=r"(a) : "l"(p));
    return a;
}
__device__ __forceinline__ void cp16(uint32_t dst, const void* src) {
    asm volatile("cp.async.cg.shared.global [%0], [%1], 16;" :: "r"(dst), "l"(src) : "memory");
}
#define CP_COMMIT() asm volatile("cp.async.commit_group;" ::: "memory")
#define CP_WAIT0()  asm volatile("cp.async.wait_group 0;" ::: "memory")
#define CP_WAIT1()  asm volatile("cp.async.wait_group 1;" ::: "memory")
__device__ __forceinline__ void ldm4t(uint32_t& r0, uint32_t& r1, uint32_t& r2, uint32_t& r3,
                                      uint32_t addr) {
    asm volatile("ldmatrix.sync.aligned.m8n8.x4.trans.shared.b16 {%0,%1,%2,%3}, [%4];"
                 : "=r"(r0), "=r"(r1), "=r"(r2), "=r"(r3) : "r"(addr));
}
__device__ __forceinline__ void mma16816(float c[4], uint32_t a0, uint32_t a1,
                                         uint32_t a2, uint32_t a3,
                                         uint32_t b0, uint32_t b1) {
    asm volatile(
        "mma.sync.aligned.m16n8k16.row.col.f32.f16.f16.f32 "
        "{%0,%1,%2,%3}, {%4,%5,%6,%7}, {%8,%9}, {%0,%1,%2,%3};"
        : "+f"(c[0]), "+f"(c[1]), "+f"(c[2]), "+f"(c[3])
        : "r"(a0), "r"(a1), "r"(a2), "r"(a3), "r"(b0), "r"(b1));
}

// =====================================================================
// prep: f16 copies (k-row-major everywhere)
// =====================================================================
__global__ void prep_kernel(const float* __restrict__ W1, const float* __restrict__ W2,
                            const float* __restrict__ W3) {
    int idx = blockIdx.x * 256 + threadIdx.x;
    if (idx < 65536) g_W2f[idx] = __float2half_rn(W2[idx]);
    else if (idx < 131072) g_W1f[idx - 65536] = __float2half_rn(W1[idx - 65536]);
    else {
        int l = idx - 131072;
        int i = l >> 6, o = l & 63;
        g_W3T[l] = __float2half_rn(W3[o * 256 + i]);
    }
}

// =====================================================================
// forward MLP (fp32 exact) + ReLU bitmasks, 16 samples / block
// =====================================================================
__global__ __launch_bounds__(256) void fwd_kernel(
    const float* __restrict__ X,
    const float* __restrict__ W1, const float* __restrict__ B1,
    const float* __restrict__ W2, const float* __restrict__ B2,
    const float* __restrict__ W3, const float* __restrict__ B3)
{
    __shared__ float bufA[16][256];
    __shared__ float bufB[16][256];
    const int t = threadIdx.x, lane = t & 31, wid = t >> 5;
    const int s0 = blockIdx.x * 16;

    {
        const float4* src = (const float4*)(X + (size_t)s0 * 256);
        float4* dst = (float4*)&bufA[0][0];
        for (int i = t; i < 16 * 64; i += 256) dst[i] = __ldg(src + i);
    }
    __syncthreads();

    float acc[16];
    {   // layer 1
        #pragma unroll
        for (int s = 0; s < 16; ++s) acc[s] = 0.f;
        const float4* wr = (const float4*)(W1 + t * 256);
        for (int j = 0; j < 64; ++j) {
            float4 w = __ldg(wr + j);
            #pragma unroll
            for (int s = 0; s < 16; ++s) {
                float4 xv = ((const float4*)bufA[s])[j];
                acc[s] = fmaf(w.x, xv.x, acc[s]); acc[s] = fmaf(w.y, xv.y, acc[s]);
                acc[s] = fmaf(w.z, xv.z, acc[s]); acc[s] = fmaf(w.w, xv.w, acc[s]);
            }
        }
        const float b = __ldg(B1 + t);
        #pragma unroll
        for (int s = 0; s < 16; ++s) {
            float z = acc[s] + b;
            unsigned m = __ballot_sync(0xffffffffu, z > 0.f);
            if (lane == 0) g_r1[(size_t)(s0 + s) * 8 + wid] = m;
            bufB[s][t] = z > 0.f ? z : 0.f;
        }
    }
    __syncthreads();
    {   // layer 2
        #pragma unroll
        for (int s = 0; s < 16; ++s) acc[s] = 0.f;
        const float4* wr = (const float4*)(W2 + t * 256);
        for (int j = 0; j < 64; ++j) {
            float4 w = __ldg(wr + j);
            #pragma unroll
            for (int s = 0; s < 16; ++s) {
                float4 xv = ((const float4*)bufB[s])[j];
                acc[s] = fmaf(w.x, xv.x, acc[s]); acc[s] = fmaf(w.y, xv.y, acc[s]);
                acc[s] = fmaf(w.z, xv.z, acc[s]); acc[s] = fmaf(w.w, xv.w, acc[s]);
            }
        }
        const float b = __ldg(B2 + t);
        #pragma unroll
        for (int s = 0; s < 16; ++s) {
            float z = acc[s] + b;
            unsigned m = __ballot_sync(0xffffffffu, z > 0.f);
            if (lane == 0) g_r2[(size_t)(s0 + s) * 8 + wid] = m;
            bufA[s][t] = z > 0.f ? z : 0.f;
        }
    }
    __syncthreads();
    {   // layer 3
        const int o = t & 63, sg = t >> 6;
        float a4[4] = {0.f, 0.f, 0.f, 0.f};
        const float4* wr = (const float4*)(W3 + o * 256);
        for (int j = 0; j < 64; ++j) {
            float4 w = __ldg(wr + j);
            #pragma unroll
            for (int q = 0; q < 4; ++q) {
                float4 hv = ((const float4*)bufA[sg * 4 + q])[j];
                a4[q] = fmaf(w.x, hv.x, a4[q]); a4[q] = fmaf(w.y, hv.y, a4[q]);
                a4[q] = fmaf(w.z, hv.z, a4[q]); a4[q] = fmaf(w.w, hv.w, a4[q]);
            }
        }
        const float b = __ldg(B3 + o);
        #pragma unroll
        for (int q = 0; q < 4; ++q)
            g_f[(size_t)(s0 + sg * 4 + q) * 64 + o] = a4[q] + b;
    }
}

// =====================================================================
// Fused persistent jac kernel: 512 threads, 16 warps (2x8, 32x32 tiles)
// Resident: W3T (257x144B), W1 (257x528B). U stays in SMEM.
// W2 active rows streamed via cp.async ring (2 x 16 rows x 528B).
// =====================================================================
#define F_W3T  0u
#define F_W1   37008u
#define F_UST  172704u
#define F_RING 209568u
#define F_MSC  226464u
#define SMEMF  228848

__global__ __launch_bounds__(512, 1) void jac_kernel(const float* __restrict__ Kp,
                                                     float* __restrict__ out) {
    extern __shared__ char smem[];
    const uint32_t sb = smem_u32(smem);
    const int tid = threadIdx.x, lane = tid & 31, wid = tid >> 5;
    const int g = lane >> 2, tig = lane & 3;
    const int wm = wid & 1, wn = wid >> 1;           // 2 x 8 warp grid

    unsigned* mbuf = (unsigned*)(smem + F_MSC);              // 2 x 16
    float*    fbuf = (float*)(smem + F_MSC + 128);           // 2 x 64
    unsigned* m2s  = (unsigned*)(smem + F_MSC + 640);        // 8
    unsigned* m1s  = (unsigned*)(smem + F_MSC + 672);        // 8
    unsigned* p2s  = (unsigned*)(smem + F_MSC + 704);        // 9(+1)
    unsigned* p1s  = (unsigned*)(smem + F_MSC + 744);        // 9(+1)
    unsigned short* idx2 = (unsigned short*)(smem + F_MSC + 784);   // 256
    unsigned short* idx1 = (unsigned short*)(smem + F_MSC + 1296);  // 256
    unsigned short* pos1 = (unsigned short*)(smem + F_MSC + 1808);  // 256
    float*    red  = (float*)(smem + F_MSC + 2320);          // 16

    // ---- resident loads ----
    for (int c = tid; c < 2048; c += 512)
        cp16(sb + F_W3T + (uint32_t)(c >> 3) * 144u + (uint32_t)(c & 7) * 16u,
             (const char*)g_W3T + (size_t)c * 16);
    for (int c = tid; c < 8192; c += 512)
        cp16(sb + F_W1 + (uint32_t)(c >> 5) * 528u + (uint32_t)(c & 31) * 16u,
             (const char*)g_W1f + (size_t)c * 16);
    // zero rows 256
    if (tid < 9)       *(uint4*)(smem + F_W3T + 256 * 144 + tid * 16) = make_uint4(0,0,0,0);
    else if (tid < 42) *(uint4*)(smem + F_W1 + 256 * 528 + (tid - 9) * 16) = make_uint4(0,0,0,0);
    // first sample masks + f
    const int s0 = blockIdx.x;
    if (tid < 2)       cp16(sb + F_MSC + tid * 16u, (const char*)(g_r2 + (size_t)s0 * 8) + tid * 16);
    else if (tid < 4)  cp16(sb + F_MSC + 32u + (tid - 2) * 16u,
                            (const char*)(g_r1 + (size_t)s0 * 8) + (tid - 2) * 16);
    else if (tid < 20) cp16(sb + F_MSC + 128u + (tid - 4) * 16u,
                            (const char*)(g_f + (size_t)s0 * 64) + (tid - 4) * 16);
    CP_COMMIT();

    const float kk = __ldg(Kp);
    const float sp = (kk > 20.f) ? kk : log1pf(expf(kk));

    const uint32_t aCol = ((lane >> 3) & 1) * 16 + (uint32_t)wm * 64u;
    const uint32_t bCol = ((lane >> 4) & 1) * 16 + (uint32_t)wn * 64u;
    const int rlA = (lane & 7) + ((lane >> 4) & 1) * 8;
    const int rlB = (lane & 7) + ((lane >> 3) & 1) * 8;

    int it = 0;
    for (int s = s0; s < B_TOT; s += NSM, ++it) {
        const int pb = it & 1;
        CP_WAIT0();
        __syncthreads();
        if (tid < 8)       m2s[tid]     = mbuf[pb * 16 + tid];
        else if (tid < 16) m1s[tid - 8] = mbuf[pb * 16 + tid];
        __syncthreads();
        if (tid == 0)  { unsigned p = 0; for (int w = 0; w < 8; ++w) { p2s[w] = p; p += __popc(m2s[w]); } p2s[8] = p; }
        if (tid == 32) { unsigned p = 0; for (int w = 0; w < 8; ++w) { p1s[w] = p; p += __popc(m1s[w]); } p1s[8] = p; }
        __syncthreads();
        const int n2 = p2s[8], n1 = p1s[8];
        int nch2 = (n2 + 15) >> 4; if (nch2 < 1) nch2 = 1;
        int nk1  = (n1 + 15) >> 4; if (nk1 < 1)  nk1 = 1;
        if (tid < 256) {
            const int w = tid >> 5, bi = tid & 31;
            const unsigned below = (bi == 0) ? 0u : ((1u << bi) - 1u);
            if ((m2s[w] >> bi) & 1u)
                idx2[p2s[w] + __popc(m2s[w] & below)] = (unsigned short)tid;
            if ((m1s[w] >> bi) & 1u) {
                unsigned p = p1s[w] + __popc(m1s[w] & below);
                idx1[p] = (unsigned short)tid;
                pos1[tid] = (unsigned short)p;
            }
            if (tid >= n2) idx2[tid] = 256;
            if (tid >= n1) idx1[tid] = 256;
        }
        // zero Ustage pad rows [n1, nk1*16)
        for (int i = tid; i < (nk1 * 16 - n1) * 9; i += 512) {
            const int r = n1 + i / 9, sg = i % 9;
            *(uint4*)(smem + F_UST + (uint32_t)r * 144u + (uint32_t)sg * 16u) = make_uint4(0,0,0,0);
        }
        __syncthreads();

        float acc[2][4][4];
        #pragma unroll
        for (int mt = 0; mt < 2; ++mt)
            #pragma unroll
            for (int nt = 0; nt < 4; ++nt)
                #pragma unroll
                for (int q = 0; q < 4; ++q) acc[mt][nt][q] = 0.f;

        // ---- GEMM1: U = (W3 D2 gathered) @ (W2 rows gathered, streamed) ----
        {
            // gather chunk c into ring slot
            auto gather = [&](int c, int slot) {
                const int r = tid >> 5, seg = tid & 31;
                const int row = idx2[c * 16 + r] & 255;
                cp16(sb + F_RING + (uint32_t)slot * 8448u + (uint32_t)r * 528u + (uint32_t)seg * 16u,
                     (const char*)g_W2f + (size_t)row * 512 + (size_t)seg * 16);
                CP_COMMIT();
            };
            gather(0, 0);
            if (nch2 > 1) gather(1, 1);
            for (int c = 0; c < nch2; ++c) {
                if (c + 1 < nch2) CP_WAIT1(); else CP_WAIT0();
                __syncthreads();
                const uint32_t rA = idx2[c * 16 + rlA];
                const uint32_t aadr = sb + F_W3T + rA * 144u + aCol;
                const uint32_t badr = sb + F_RING + (uint32_t)(c & 1) * 8448u
                                        + (uint32_t)rlB * 528u + bCol;
                uint32_t a[2][4], b[2][4];
                #pragma unroll
                for (int mt = 0; mt < 2; ++mt)
                    ldm4t(a[mt][0], a[mt][1], a[mt][2], a[mt][3], aadr + (uint32_t)mt * 32u);
                #pragma unroll
                for (int ng = 0; ng < 2; ++ng)
                    ldm4t(b[ng][0], b[ng][1], b[ng][2], b[ng][3], badr + (uint32_t)ng * 32u);
                #pragma unroll
                for (int mt = 0; mt < 2; ++mt)
                    #pragma unroll
                    for (int nt = 0; nt < 4; ++nt)
                        mma16816(acc[mt][nt], a[mt][0], a[mt][1], a[mt][2], a[mt][3],
                                 b[nt >> 1][(nt & 1) * 2], b[nt >> 1][(nt & 1) * 2 + 1]);
                __syncthreads();
                if (c + 2 < nch2) gather(c + 2, c & 1);
            }
        }

        // ---- scatter masked U (compact rows, pitch 144) ----
        #pragma unroll
        for (int mt = 0; mt < 2; ++mt)
            #pragma unroll
            for (int nt = 0; nt < 4; ++nt)
                #pragma unroll
                for (int q = 0; q < 4; ++q) {
                    const int m = wm * 32 + mt * 16 + g + (q >> 1) * 8;
                    const int j = wn * 32 + nt * 8 + 2 * tig + (q & 1);
                    if ((m1s[j >> 5] >> (j & 31)) & 1u)
                        *(__half*)(smem + F_UST + (uint32_t)pos1[j] * 144u + (uint32_t)m * 2u) =
                            __float2half_rn(acc[mt][nt][q]);
                    acc[mt][nt][q] = 0.f;
                }
        // prefetch next sample masks + f
        {
            const int sn = s + NSM;
            if (sn < B_TOT) {
                const uint32_t mb = sb + F_MSC + (uint32_t)(pb ^ 1) * 64u;
                const uint32_t fb = sb + F_MSC + 128u + (uint32_t)(pb ^ 1) * 256u;
                if (tid < 2)       cp16(mb + tid * 16u, (const char*)(g_r2 + (size_t)sn * 8) + tid * 16);
                else if (tid < 4)  cp16(mb + 32u + (tid - 2) * 16u,
                                        (const char*)(g_r1 + (size_t)sn * 8) + (tid - 2) * 16);
                else if (tid < 20) cp16(fb + (tid - 4) * 16u,
                                        (const char*)(g_f + (size_t)sn * 64) + (tid - 4) * 16);
            }
            CP_COMMIT();
        }
        __syncthreads();

        // ---- GEMM2: V = U @ (W1 rows gathered, resident) ----
        for (int kt = 0; kt < nk1; ++kt) {
            const uint32_t rB = idx1[kt * 16 + rlB];
            const uint32_t aadr = sb + F_UST + (uint32_t)(kt * 16 + rlA) * 144u + aCol;
            const uint32_t badr = sb + F_W1 + rB * 528u + bCol;
            uint32_t a[2][4], b[2][4];
            #pragma unroll
            for (int mt = 0; mt < 2; ++mt)
                ldm4t(a[mt][0], a[mt][1], a[mt][2], a[mt][3], aadr + (uint32_t)mt * 32u);
            #pragma unroll
            for (int ng = 0; ng < 2; ++ng)
                ldm4t(b[ng][0], b[ng][1], b[ng][2], b[ng][3], badr + (uint32_t)ng * 32u);
            #pragma unroll
            for (int mt = 0; mt < 2; ++mt)
                #pragma unroll
                for (int nt = 0; nt < 4; ++nt)
                    mma16816(acc[mt][nt], a[mt][0], a[mt][1], a[mt][2], a[mt][3],
                             b[nt >> 1][(nt & 1) * 2], b[nt >> 1][(nt & 1) * 2 + 1]);
        }

        // ---- ||J||^2 + epilogue ----
        float ss = 0.f;
        #pragma unroll
        for (int mt = 0; mt < 2; ++mt)
            #pragma unroll
            for (int nt = 0; nt < 4; ++nt)
                #pragma unroll
                for (int q = 0; q < 4; ++q)
                    ss = fmaf(acc[mt][nt][q], acc[mt][nt][q], ss);
        #pragma unroll
        for (int off = 16; off; off >>= 1)
            ss += __shfl_xor_sync(0xffffffffu, ss, off);
        if (lane == 0) red[wid] = ss;
        __syncthreads();

        if (tid < 64) {
            float jn2 = 0.f;
            #pragma unroll
            for (int w = 0; w < 16; ++w) jn2 += red[w];
            const float fv = fbuf[pb * 64 + tid];
            out[(size_t)s * 64 + tid] = tanhf(sp * fv / (sqrtf(jn2) + 1e-4f));
        }
        __syncthreads();
    }
}

// =====================================================================
extern "C" void kernel_launch(void* const* d_in, const int* in_sizes, int n_in,
                              void* d_out, int out_size)
{
    const float* X  = (const float*)d_in[0];
    const float* W1 = (const float*)d_in[1];
    const float* B1 = (const float*)d_in[2];
    const float* W2 = (const float*)d_in[3];
    const float* B2 = (const float*)d_in[4];
    const float* W3 = (const float*)d_in[5];
    const float* B3 = (const float*)d_in[6];
    const float* Kp = (const float*)d_in[7];
    float* out = (float*)d_out;

    cudaFuncSetAttribute(jac_kernel, cudaFuncAttributeMaxDynamicSharedMemorySize, SMEMF);

    prep_kernel<<<576, 256>>>(W1, W2, W3);
    fwd_kernel<<<B_TOT / 16, 256>>>(X, W1, B1, W2, B2, W3, B3);
    jac_kernel<<<NSM, 512, SMEMF>>>(Kp, out);
}